// round 1
// baseline (speedup 1.0000x reference)
#include <cuda_runtime.h>
#include <math.h>

#define B 32
#define C 256
#define HW 56
#define BC (B*C)
#define POOL 7
#define GS 8           // pooled grid 8x8
#define NN 64          // pooled spatial n = 64
#define HEADS 8
#define HD 32          // head dim
#define EPS 1e-5f

// ---------------- scratch (device globals: allocation-free) ----------------
__device__ float g_mean_h[BC * HW];
__device__ float g_mean_w[BC * HW];
__device__ float g_attn_h[BC * HW];
__device__ float g_attn_w[BC * HW];
__device__ float g_pooled[BC * NN];
__device__ float g_mu[B];
__device__ float g_rstd[B];
__device__ float g_ca[BC];

// ---------------- kernel 1: row & col means of each 56x56 plane ------------
__global__ __launch_bounds__(256) void k_means(const float* __restrict__ x) {
    __shared__ float sp[HW][HW + 1];   // padded stride 57 -> conflict-free both ways
    __shared__ float scol[4][64];
    int bc = blockIdx.x;
    const float* xp = x + (size_t)bc * HW * HW;
    int tx = threadIdx.x;  // 0..63
    int ty = threadIdx.y;  // 0..3
    float colpart = 0.f;
    if (tx < HW) {
        #pragma unroll
        for (int it = 0; it < 14; ++it) {
            int h = ty + 4 * it;
            float v = xp[h * HW + tx];
            sp[h][tx] = v;
            colpart += v;
        }
    }
    scol[ty][tx] = colpart;
    __syncthreads();
    int tid = ty * 64 + tx;
    if (tid < HW) {
        float cs = scol[0][tid] + scol[1][tid] + scol[2][tid] + scol[3][tid];
        g_mean_w[bc * HW + tid] = cs * (1.f / 56.f);     // mean over h (axis=2)
        float rs = 0.f;
        #pragma unroll
        for (int w = 0; w < HW; ++w) rs += sp[tid][w];
        g_mean_h[bc * HW + tid] = rs * (1.f / 56.f);     // mean over w (axis=3)
    }
}

// ---------------- kernel 2: sa_branch (dwconv -> GN(4) -> sigmoid) ---------
// grid: (group=4, batch=32, branch=2), block: 256
__global__ __launch_bounds__(256) void k_sa(
    const float* __restrict__ w3, const float* __restrict__ b3,
    const float* __restrict__ w5, const float* __restrict__ b5,
    const float* __restrict__ w7, const float* __restrict__ b7,
    const float* __restrict__ w9, const float* __restrict__ b9,
    const float* __restrict__ sh, const float* __restrict__ bh,
    const float* __restrict__ sw, const float* __restrict__ bw)
{
    __shared__ float sin_[64 * HW];
    __shared__ float sy_[64 * HW];
    __shared__ float r1[8], r2[8], sstat[2];

    int g  = blockIdx.x;
    int b  = blockIdx.y;
    int br = blockIdx.z;
    const float* in  = (br == 0) ? g_mean_h : g_mean_w;
    float*       out = (br == 0) ? g_attn_h : g_attn_w;
    const float* sc  = (br == 0) ? sh : sw;
    const float* bi  = (br == 0) ? bh : bw;
    const float* wf; const float* bf; int ksz;
    if (g == 0)      { wf = w3; bf = b3; ksz = 3; }
    else if (g == 1) { wf = w5; bf = b5; ksz = 5; }
    else if (g == 2) { wf = w7; bf = b7; ksz = 7; }
    else             { wf = w9; bf = b9; ksz = 9; }
    int pad = ksz >> 1;

    int tid = threadIdx.x;
    size_t base = ((size_t)b * C + g * 64) * HW;
    for (int i = tid; i < 64 * HW; i += 256) sin_[i] = in[base + i];
    __syncthreads();

    float s = 0.f, ss = 0.f;
    for (int i = tid; i < 64 * HW; i += 256) {
        int c = i / HW, l = i - c * HW;
        float acc = bf[c];
        for (int j = 0; j < ksz; ++j) {
            int idx = l + j - pad;
            if (idx >= 0 && idx < HW) acc = fmaf(wf[c * ksz + j], sin_[c * HW + idx], acc);
        }
        sy_[i] = acc;
        s += acc; ss = fmaf(acc, acc, ss);
    }
    // block reduce (sum, sumsq) over 3584 values
    int lane = tid & 31, wid = tid >> 5;
    #pragma unroll
    for (int o = 16; o; o >>= 1) { s += __shfl_xor_sync(~0u, s, o); ss += __shfl_xor_sync(~0u, ss, o); }
    if (lane == 0) { r1[wid] = s; r2[wid] = ss; }
    __syncthreads();
    if (tid == 0) {
        float a = 0.f, bsum = 0.f;
        #pragma unroll
        for (int w = 0; w < 8; ++w) { a += r1[w]; bsum += r2[w]; }
        float mean = a * (1.f / 3584.f);
        float var  = bsum * (1.f / 3584.f) - mean * mean;
        sstat[0] = mean;
        sstat[1] = rsqrtf(var + EPS);
    }
    __syncthreads();
    float mean = sstat[0], rstd = sstat[1];
    for (int i = tid; i < 64 * HW; i += 256) {
        int c = i / HW;
        int cg = g * 64 + c;
        float yn = (sy_[i] - mean) * rstd * sc[cg] + bi[cg];
        out[base + i] = 1.f / (1.f + expf(-yn));
    }
}

// ---------------- kernel 3: pooled sums of xg = x*ah*aw (7x7 avgpool) ------
__global__ __launch_bounds__(256) void k_pool(const float* __restrict__ x) {
    __shared__ float sp[HW][HW + 1];
    __shared__ float sah[HW], saw[HW];
    int bc = blockIdx.x;
    const float* xp = x + (size_t)bc * HW * HW;
    int tx = threadIdx.x, ty = threadIdx.y;
    int tid = ty * 64 + tx;
    if (tid < HW)                     sah[tid] = g_attn_h[bc * HW + tid];
    else if (tid >= 64 && tid < 120)  saw[tid - 64] = g_attn_w[bc * HW + tid - 64];
    __syncthreads();
    if (tx < HW) {
        float aw = saw[tx];
        #pragma unroll
        for (int it = 0; it < 14; ++it) {
            int h = ty + 4 * it;
            sp[h][tx] = xp[h * HW + tx] * sah[h] * aw;
        }
    }
    __syncthreads();
    if (tid < NN) {
        int i = tid >> 3, j = tid & 7;
        float sum = 0.f;
        #pragma unroll
        for (int u = 0; u < POOL; ++u)
            #pragma unroll
            for (int v = 0; v < POOL; ++v)
                sum += sp[POOL * i + u][POOL * j + v];
        g_pooled[bc * NN + tid] = sum * (1.f / 49.f);
    }
}

// ---------------- kernel 4a: layer-norm stats per batch --------------------
__global__ __launch_bounds__(256) void k_stats() {
    __shared__ float r1[8], r2[8];
    int b = blockIdx.x, tid = threadIdx.x;
    const float* p = g_pooled + (size_t)b * C * NN;
    float s = 0.f, ss = 0.f;
    for (int i = tid; i < C * NN; i += 256) { float v = p[i]; s += v; ss = fmaf(v, v, ss); }
    int lane = tid & 31, wid = tid >> 5;
    #pragma unroll
    for (int o = 16; o; o >>= 1) { s += __shfl_xor_sync(~0u, s, o); ss += __shfl_xor_sync(~0u, ss, o); }
    if (lane == 0) { r1[wid] = s; r2[wid] = ss; }
    __syncthreads();
    if (tid == 0) {
        float a = 0.f, bsum = 0.f;
        #pragma unroll
        for (int w = 0; w < 8; ++w) { a += r1[w]; bsum += r2[w]; }
        float mean = a * (1.f / 16384.f);
        float var  = bsum * (1.f / 16384.f) - mean * mean;
        g_mu[b]   = mean;
        g_rstd[b] = rsqrtf(var + EPS);
    }
}

// ---------------- kernel 4b: per (b,head) attention -> channel gate --------
// grid: (head=8, batch=32), block: 128 (4 warps, 8 d-rows each)
__global__ __launch_bounds__(128) void k_attn(
    const float* __restrict__ ns, const float* __restrict__ nb,
    const float* __restrict__ qw, const float* __restrict__ kw,
    const float* __restrict__ vw)
{
    __shared__ float xs[HD][NN + 1];   // padded stride 65 -> conflict-free column reads
    __shared__ float svbar[HD];
    int h = blockIdx.x, b = blockIdx.y;
    float mu = g_mu[b], rstd = g_rstd[b];
    const float* p = g_pooled + ((size_t)b * C + h * HD) * NN;
    int tid = threadIdx.x;
    for (int i = tid; i < HD * NN; i += 128) {
        int e = i >> 6, n = i & 63;
        int c = h * HD + e;
        xs[e][n] = (p[i] - mu) * rstd * ns[c] + nb[c];
    }
    __syncthreads();
    if (tid < HD) {
        float s = 0.f;
        #pragma unroll
        for (int n = 0; n < NN; ++n) s += xs[tid][n];
        svbar[tid] = s * (1.f / 64.f) * vw[h * HD + tid];
    }
    __syncthreads();

    int wi = tid >> 5, lane = tid & 31;
    float xe[NN];
    #pragma unroll
    for (int n = 0; n < NN; ++n) xe[n] = xs[lane][n];     // k-row cached in regs
    float kwe = kw[h * HD + lane];
    float vb  = svbar[lane];
    const float scale = 0.17677669529663687f;             // 32^-0.5

    #pragma unroll
    for (int dd = 0; dd < 8; ++dd) {
        int d = wi * 8 + dd;
        float dot = 0.f;
        #pragma unroll
        for (int n = 0; n < NN; ++n) dot = fmaf(xs[d][n], xe[n], dot);
        float s = dot * qw[h * HD + d] * kwe * scale;
        float m = s;
        #pragma unroll
        for (int o = 16; o; o >>= 1) m = fmaxf(m, __shfl_xor_sync(~0u, m, o));
        float pe = expf(s - m);
        float Z = pe;
        #pragma unroll
        for (int o = 16; o; o >>= 1) Z += __shfl_xor_sync(~0u, Z, o);
        float contrib = (pe / Z) * vb;
        #pragma unroll
        for (int o = 16; o; o >>= 1) contrib += __shfl_xor_sync(~0u, contrib, o);
        if (lane == 0)
            g_ca[b * C + h * HD + d] = 1.f / (1.f + expf(-contrib));
    }
}

// ---------------- kernel 5: out = ca * x * ah * aw (float4) ----------------
__global__ __launch_bounds__(256) void k_final(const float* __restrict__ x,
                                               float* __restrict__ out) {
    __shared__ float sah[HW], saw[HW];
    int bc = blockIdx.x, tid = threadIdx.x;
    if (tid < HW)                     sah[tid] = g_attn_h[bc * HW + tid];
    else if (tid >= 64 && tid < 120)  saw[tid - 64] = g_attn_w[bc * HW + tid - 64];
    float ca = g_ca[bc];
    __syncthreads();
    const float4* xp = (const float4*)(x + (size_t)bc * HW * HW);
    float4*       op = (float4*)(out + (size_t)bc * HW * HW);
    // 56*56 = 3136 floats = 784 float4; 14 float4 per row (56 % 4 == 0)
    for (int f = tid; f < 784; f += 256) {
        int hrow = f / 14;
        int w4   = (f - hrow * 14) * 4;
        float4 v = xp[f];
        float s = ca * sah[hrow];
        v.x *= s * saw[w4 + 0];
        v.y *= s * saw[w4 + 1];
        v.z *= s * saw[w4 + 2];
        v.w *= s * saw[w4 + 3];
        op[f] = v;
    }
}

// ---------------- launch ---------------------------------------------------
extern "C" void kernel_launch(void* const* d_in, const int* in_sizes, int n_in,
                              void* d_out, int out_size) {
    const float* x  = (const float*)d_in[0];
    const float* w3 = (const float*)d_in[1];
    const float* b3 = (const float*)d_in[2];
    const float* w5 = (const float*)d_in[3];
    const float* b5 = (const float*)d_in[4];
    const float* w7 = (const float*)d_in[5];
    const float* b7 = (const float*)d_in[6];
    const float* w9 = (const float*)d_in[7];
    const float* b9 = (const float*)d_in[8];
    const float* nhs = (const float*)d_in[9];
    const float* nhb = (const float*)d_in[10];
    const float* nws = (const float*)d_in[11];
    const float* nwb = (const float*)d_in[12];
    const float* ns  = (const float*)d_in[13];
    const float* nb  = (const float*)d_in[14];
    const float* qw  = (const float*)d_in[15];
    const float* kw  = (const float*)d_in[16];
    const float* vw  = (const float*)d_in[17];
    float* out = (float*)d_out;

    k_means<<<BC, dim3(64, 4)>>>(x);
    k_sa<<<dim3(4, B, 2), 256>>>(w3, b3, w5, b5, w7, b7, w9, b9, nhs, nhb, nws, nwb);
    k_pool<<<BC, dim3(64, 4)>>>(x);
    k_stats<<<B, 256>>>();
    k_attn<<<dim3(HEADS, B), 128>>>(ns, nb, qw, kw, vw);
    k_final<<<BC, 256>>>(x, out);
}

// round 2
// speedup vs baseline: 1.3509x; 1.3509x over previous
#include <cuda_runtime.h>
#include <math.h>

#define B 32
#define C 256
#define HW 56
#define BC (B*C)
#define POOL 7
#define NN 64          // pooled spatial n = 64
#define HEADS 8
#define HD 32          // head dim
#define EPS 1e-5f

// ---------------- scratch (device globals: allocation-free) ----------------
__device__ float g_mean_h[BC * HW];
__device__ float g_mean_w[BC * HW];
__device__ float g_attn_h[BC * HW];
__device__ float g_attn_w[BC * HW];
__device__ float g_pooled[BC * NN];
__device__ float g_bsum[B];
__device__ float g_bsumsq[B];
__device__ float g_ca[BC];

// ---------------- kernel 1: row & col means of each 56x56 plane ------------
// One plane per block, 256 threads, float4 global loads (784 float4/plane).
__global__ __launch_bounds__(256) void k_means(const float* __restrict__ x) {
    __shared__ float sp[HW][HW + 1];   // stride 57: conflict-free row+col reads
    int bc = blockIdx.x, tid = threadIdx.x;
    if (tid == 0 && bc < B) { g_bsum[bc] = 0.f; g_bsumsq[bc] = 0.f; }
    const float4* xp = (const float4*)(x + (size_t)bc * HW * HW);
    #pragma unroll
    for (int k = 0; k < 4; ++k) {
        int f = tid + 256 * k;
        if (f < 784) {
            float4 v = xp[f];
            int r = f / 14, c = (f - r * 14) * 4;
            sp[r][c]     = v.x;
            sp[r][c + 1] = v.y;
            sp[r][c + 2] = v.z;
            sp[r][c + 3] = v.w;
        }
    }
    __syncthreads();
    if (tid < HW) {
        float rs = 0.f, cs = 0.f;
        #pragma unroll
        for (int w = 0; w < HW; ++w) { rs += sp[tid][w]; cs += sp[w][tid]; }
        g_mean_h[bc * HW + tid] = rs * (1.f / 56.f);   // mean over w (axis=3)
        g_mean_w[bc * HW + tid] = cs * (1.f / 56.f);   // mean over h (axis=2)
    }
}

// ---------------- kernel 2: sa_branch (dwconv -> GN(4) -> sigmoid) ---------
// grid: (group=4, batch=32, branch=2), block: 256
__global__ __launch_bounds__(256) void k_sa(
    const float* __restrict__ w3, const float* __restrict__ b3,
    const float* __restrict__ w5, const float* __restrict__ b5,
    const float* __restrict__ w7, const float* __restrict__ b7,
    const float* __restrict__ w9, const float* __restrict__ b9,
    const float* __restrict__ sh, const float* __restrict__ bh,
    const float* __restrict__ sw, const float* __restrict__ bw)
{
    __shared__ float sin_[64 * HW];
    __shared__ float sy_[64 * HW];
    __shared__ float r1[8], r2[8], sstat[2];

    int g  = blockIdx.x;
    int b  = blockIdx.y;
    int br = blockIdx.z;
    const float* in  = (br == 0) ? g_mean_h : g_mean_w;
    float*       out = (br == 0) ? g_attn_h : g_attn_w;
    const float* sc  = (br == 0) ? sh : sw;
    const float* bi  = (br == 0) ? bh : bw;
    const float* wf; const float* bf; int ksz;
    if (g == 0)      { wf = w3; bf = b3; ksz = 3; }
    else if (g == 1) { wf = w5; bf = b5; ksz = 5; }
    else if (g == 2) { wf = w7; bf = b7; ksz = 7; }
    else             { wf = w9; bf = b9; ksz = 9; }
    int pad = ksz >> 1;

    int tid = threadIdx.x;
    size_t base = ((size_t)b * C + g * 64) * HW;
    for (int i = tid; i < 64 * HW; i += 256) sin_[i] = in[base + i];
    __syncthreads();

    float s = 0.f, ss = 0.f;
    for (int i = tid; i < 64 * HW; i += 256) {
        int c = i / HW, l = i - c * HW;
        float acc = bf[c];
        for (int j = 0; j < ksz; ++j) {
            int idx = l + j - pad;
            if (idx >= 0 && idx < HW) acc = fmaf(wf[c * ksz + j], sin_[c * HW + idx], acc);
        }
        sy_[i] = acc;
        s += acc; ss = fmaf(acc, acc, ss);
    }
    int lane = tid & 31, wid = tid >> 5;
    #pragma unroll
    for (int o = 16; o; o >>= 1) { s += __shfl_xor_sync(~0u, s, o); ss += __shfl_xor_sync(~0u, ss, o); }
    if (lane == 0) { r1[wid] = s; r2[wid] = ss; }
    __syncthreads();
    if (tid == 0) {
        float a = 0.f, bsum = 0.f;
        #pragma unroll
        for (int w = 0; w < 8; ++w) { a += r1[w]; bsum += r2[w]; }
        float mean = a * (1.f / 3584.f);
        float var  = bsum * (1.f / 3584.f) - mean * mean;
        sstat[0] = mean;
        sstat[1] = rsqrtf(var + EPS);
    }
    __syncthreads();
    float mean = sstat[0], rstd = sstat[1];
    for (int i = tid; i < 64 * HW; i += 256) {
        int c = i / HW;
        int cg = g * 64 + c;
        float yn = (sy_[i] - mean) * rstd * sc[cg] + bi[cg];
        out[base + i] = 1.f / (1.f + expf(-yn));
    }
}

// ---------------- kernel 3: pooled sums of xg = x*ah*aw (7x7 avgpool) ------
// float4 loads; also accumulates per-batch sum/sumsq (kills k_stats)
__global__ __launch_bounds__(256) void k_pool(const float* __restrict__ x) {
    __shared__ float sp[HW][HW + 1];
    __shared__ float sah[HW], saw[HW];
    __shared__ float rs_[2], rss_[2];
    int bc = blockIdx.x, tid = threadIdx.x;
    int b = bc >> 8;   // bc / C
    if (tid < HW) { sah[tid] = g_attn_h[bc * HW + tid]; saw[tid] = g_attn_w[bc * HW + tid]; }
    __syncthreads();
    const float4* xp = (const float4*)(x + (size_t)bc * HW * HW);
    #pragma unroll
    for (int k = 0; k < 4; ++k) {
        int f = tid + 256 * k;
        if (f < 784) {
            float4 v = xp[f];
            int r = f / 14, c = (f - r * 14) * 4;
            float a = sah[r];
            sp[r][c]     = v.x * a * saw[c];
            sp[r][c + 1] = v.y * a * saw[c + 1];
            sp[r][c + 2] = v.z * a * saw[c + 2];
            sp[r][c + 3] = v.w * a * saw[c + 3];
        }
    }
    __syncthreads();
    float pv = 0.f;
    if (tid < NN) {
        int i = tid >> 3, j = tid & 7;
        float sum = 0.f;
        #pragma unroll
        for (int u = 0; u < POOL; ++u)
            #pragma unroll
            for (int v = 0; v < POOL; ++v)
                sum += sp[POOL * i + u][POOL * j + v];
        pv = sum * (1.f / 49.f);
        g_pooled[bc * NN + tid] = pv;
    }
    // reduce sum & sumsq of the 64 pooled values -> atomic into per-batch accum
    if (tid < NN) {
        float s = pv, ss = pv * pv;
        #pragma unroll
        for (int o = 16; o; o >>= 1) { s += __shfl_xor_sync(~0u, s, o); ss += __shfl_xor_sync(~0u, ss, o); }
        int lane = tid & 31, wid = tid >> 5;
        if (lane == 0) { rs_[wid] = s; rss_[wid] = ss; }
    }
    __syncthreads();
    if (tid == 0) {
        atomicAdd(&g_bsum[b],   rs_[0] + rs_[1]);
        atomicAdd(&g_bsumsq[b], rss_[0] + rss_[1]);
    }
}

// ---------------- kernel 4: per (b,head) attention -> channel gate ---------
// grid: (head=8, batch=32), block: 128 (4 warps, 8 d-rows each)
__global__ __launch_bounds__(128) void k_attn(
    const float* __restrict__ ns, const float* __restrict__ nb,
    const float* __restrict__ qw, const float* __restrict__ kw,
    const float* __restrict__ vw)
{
    __shared__ float xs[HD][NN + 1];
    __shared__ float svbar[HD];
    int h = blockIdx.x, b = blockIdx.y;
    float bs = g_bsum[b], bss = g_bsumsq[b];
    float mu = bs * (1.f / 16384.f);
    float var = bss * (1.f / 16384.f) - mu * mu;
    float rstd = rsqrtf(var + EPS);
    const float* p = g_pooled + ((size_t)b * C + h * HD) * NN;
    int tid = threadIdx.x;
    for (int i = tid; i < HD * NN; i += 128) {
        int e = i >> 6;
        int c = h * HD + e;
        xs[e][i & 63] = (p[i] - mu) * rstd * ns[c] + nb[c];
    }
    __syncthreads();
    if (tid < HD) {
        float s = 0.f;
        #pragma unroll
        for (int n = 0; n < NN; ++n) s += xs[tid][n];
        svbar[tid] = s * (1.f / 64.f) * vw[h * HD + tid];
    }
    __syncthreads();

    int wi = tid >> 5, lane = tid & 31;
    float xe[NN];
    #pragma unroll
    for (int n = 0; n < NN; ++n) xe[n] = xs[lane][n];
    float kwe = kw[h * HD + lane];
    float vb  = svbar[lane];
    const float scale = 0.17677669529663687f;   // 32^-0.5

    #pragma unroll
    for (int dd = 0; dd < 8; ++dd) {
        int d = wi * 8 + dd;
        float dot = 0.f;
        #pragma unroll
        for (int n = 0; n < NN; ++n) dot = fmaf(xs[d][n], xe[n], dot);
        float s = dot * qw[h * HD + d] * kwe * scale;
        float m = s;
        #pragma unroll
        for (int o = 16; o; o >>= 1) m = fmaxf(m, __shfl_xor_sync(~0u, m, o));
        float pe = expf(s - m);
        float Z = pe;
        #pragma unroll
        for (int o = 16; o; o >>= 1) Z += __shfl_xor_sync(~0u, Z, o);
        float contrib = (pe / Z) * vb;
        #pragma unroll
        for (int o = 16; o; o >>= 1) contrib += __shfl_xor_sync(~0u, contrib, o);
        if (lane == 0)
            g_ca[b * C + h * HD + d] = 1.f / (1.f + expf(-contrib));
    }
}

// ---------------- kernel 5: out = ca * x * ah * aw (float4, unrolled) ------
__global__ __launch_bounds__(256) void k_final(const float* __restrict__ x,
                                               float* __restrict__ out) {
    __shared__ float sah[HW], saw[HW];
    int bc = blockIdx.x, tid = threadIdx.x;
    if (tid < HW)                     sah[tid] = g_attn_h[bc * HW + tid];
    else if (tid >= 64 && tid < 120)  saw[tid - 64] = g_attn_w[bc * HW + tid - 64];
    float ca = g_ca[bc];
    __syncthreads();
    const float4* xp = (const float4*)(x + (size_t)bc * HW * HW);
    float4*       op = (float4*)(out + (size_t)bc * HW * HW);
    // front-batch the 4 loads for MLP
    float4 v[4]; int f[4]; bool valid[4];
    #pragma unroll
    for (int k = 0; k < 4; ++k) {
        f[k] = tid + 256 * k;
        valid[k] = (f[k] < 784);
        if (valid[k]) v[k] = xp[f[k]];
    }
    #pragma unroll
    for (int k = 0; k < 4; ++k) {
        if (valid[k]) {
            int hrow = f[k] / 14;
            int w4   = (f[k] - hrow * 14) * 4;
            float s = ca * sah[hrow];
            float4 o = v[k];
            o.x *= s * saw[w4 + 0];
            o.y *= s * saw[w4 + 1];
            o.z *= s * saw[w4 + 2];
            o.w *= s * saw[w4 + 3];
            op[f[k]] = o;
        }
    }
}

// ---------------- launch ---------------------------------------------------
extern "C" void kernel_launch(void* const* d_in, const int* in_sizes, int n_in,
                              void* d_out, int out_size) {
    const float* x  = (const float*)d_in[0];
    const float* w3 = (const float*)d_in[1];
    const float* b3 = (const float*)d_in[2];
    const float* w5 = (const float*)d_in[3];
    const float* b5 = (const float*)d_in[4];
    const float* w7 = (const float*)d_in[5];
    const float* b7 = (const float*)d_in[6];
    const float* w9 = (const float*)d_in[7];
    const float* b9 = (const float*)d_in[8];
    const float* nhs = (const float*)d_in[9];
    const float* nhb = (const float*)d_in[10];
    const float* nws = (const float*)d_in[11];
    const float* nwb = (const float*)d_in[12];
    const float* ns  = (const float*)d_in[13];
    const float* nb  = (const float*)d_in[14];
    const float* qw  = (const float*)d_in[15];
    const float* kw  = (const float*)d_in[16];
    const float* vw  = (const float*)d_in[17];
    float* out = (float*)d_out;

    k_means<<<BC, 256>>>(x);
    k_sa<<<dim3(4, B, 2), 256>>>(w3, b3, w5, b5, w7, b7, w9, b9, nhs, nhb, nws, nwb);
    k_pool<<<BC, 256>>>(x);
    k_attn<<<dim3(HEADS, B), 128>>>(ns, nb, qw, kw, vw);
    k_final<<<BC, 256>>>(x, out);
}